// round 16
// baseline (speedup 1.0000x reference)
#include <cuda_runtime.h>
#include <cuda_fp16.h>
#include <cstdint>

#define BATCH 16
#define HIN 32
#define WIN 32
#define CH 512
#define HOUT 64
#define WOUT 64
#define WSCALE 0.014731391274719742f

__device__ float g_s1[BATCH][CH];
__device__ float g_s2[BATCH][CH];
__device__ float g_sr[BATCH][CH];
__device__ float g_d1[BATCH][CH];
__device__ float g_d2[BATCH][CH];
__device__ float g_wsq1[CH * CH];
__device__ float g_wsq2[CH * CH];
__device__ float g_y[(size_t)BATCH * HOUT * WOUT * CH];
__device__ uint32_t g_xh[(size_t)BATCH * HIN * WIN * 256];
__device__ uint32_t g_x1h[(size_t)BATCH * HOUT * WOUT * 256];
#define WSPN (9 * 4 * 16 * 32 * 128)
__device__ uint32_t g_wspA[WSPN];
__device__ uint32_t g_wspB[WSPN];

__device__ __forceinline__ float lrelu(float v) { return v > 0.f ? v : 0.2f * v; }

__device__ __forceinline__ uint32_t smem_u32(const void* p) {
    uint32_t a;
    asm("{ .reg .u64 t; cvta.to.shared.u64 t, %1; cvt.u32.u64 %0, t; }" : "=r"(a) : "l"(p));
    return a;
}
__device__ __forceinline__ uint32_t pack_f16(float f0, float f1) {
    __half2 h = __floats2half2_rn(f0, f1);
    return *(uint32_t*)&h;
}
__device__ __forceinline__ float2 unpack_f16(uint32_t p) {
    __half2 h = *(__half2*)&p;
    return __half22float2(h);
}
__device__ __forceinline__ void mma16(float* d, const uint32_t* a, uint32_t b0, uint32_t b1) {
    asm volatile(
        "mma.sync.aligned.m16n8k16.row.col.f32.f16.f16.f32 "
        "{%0,%1,%2,%3},{%4,%5,%6,%7},{%8,%9},{%0,%1,%2,%3};"
        : "+f"(d[0]), "+f"(d[1]), "+f"(d[2]), "+f"(d[3])
        : "r"(a[0]), "r"(a[1]), "r"(a[2]), "r"(a[3]), "r"(b0), "r"(b1));
}
__device__ __forceinline__ void lds128(uint32_t* r, uint32_t a) {
    asm volatile("ld.shared.v4.b32 {%0,%1,%2,%3},[%4];"
                 : "=r"(r[0]), "=r"(r[1]), "=r"(r[2]), "=r"(r[3]) : "r"(a));
}
__device__ __forceinline__ void sts32(uint32_t a, uint32_t v) {
    asm volatile("st.shared.b32 [%0],%1;" :: "r"(a), "r"(v) : "memory");
}
__device__ __forceinline__ void cpa16(uint32_t dst, const uint32_t* src) {
    asm volatile("cp.async.cg.shared.global [%0], [%1], 16;"
                 :: "r"(dst), "l"(src) : "memory");
}
#define CP_COMMIT() asm volatile("cp.async.commit_group;" ::: "memory")
#define CP_WAIT0() asm volatile("cp.async.wait_group 0;" ::: "memory")

__global__ void k_styles(const float* __restrict__ w,
                         const float* __restrict__ f1w, const float* __restrict__ f1b,
                         const float* __restrict__ f2w, const float* __restrict__ f2b,
                         const float* __restrict__ frw, const float* __restrict__ frb) {
    int b = blockIdx.x, which = blockIdx.y, co = threadIdx.x;
    const float* fw = which == 0 ? f1w : (which == 1 ? f2w : frw);
    const float* fb = which == 0 ? f1b : (which == 1 ? f2b : frb);
    __shared__ float sw_[CH];
    sw_[co] = w[b * CH + co];
    __syncthreads();
    float acc = 0.f;
#pragma unroll 4
    for (int ci = 0; ci < CH; ci++) acc = fmaf(sw_[ci], fw[ci * CH + co], acc);
    float v = acc * 0.044194173824159216f + fb[co];
    if (which == 0) g_s1[b][co] = v;
    else if (which == 1) g_s2[b][co] = v;
    else g_sr[b][co] = v;
}

__global__ void k_wsq(const float* __restrict__ w1, const float* __restrict__ w2) {
    int idx = blockIdx.x * 256 + threadIdx.x;
    const float ws2 = 1.0f / 4608.0f;
    float a1 = 0.f, a2 = 0.f;
#pragma unroll
    for (int t = 0; t < 9; t++) {
        float v1 = w1[(size_t)t * CH * CH + idx];
        a1 = fmaf(v1, v1, a1);
        float v2 = w2[(size_t)t * CH * CH + idx];
        a2 = fmaf(v2, v2, a2);
    }
    g_wsq1[idx] = a1 * ws2;
    g_wsq2[idx] = a2 * ws2;
}

__global__ void k_demod() {
    int b = blockIdx.x, which = blockIdx.y, co = threadIdx.x;
    __shared__ float ss[CH];
    float s = which ? g_s2[b][co] : g_s1[b][co];
    ss[co] = s * s;
    __syncthreads();
    const float* wsq = which ? g_wsq2 : g_wsq1;
    float acc = 0.f;
#pragma unroll 4
    for (int ci = 0; ci < CH; ci++) acc = fmaf(ss[ci], wsq[ci * CH + co], acc);
    float d = rsqrtf(acc + 1e-8f);
    if (which) g_d2[b][co] = d;
    else g_d1[b][co] = d;
}

__global__ void k_wsplit(const float* __restrict__ cw, int which) {
    uint32_t* __restrict__ out = which ? g_wspB : g_wspA;
    int bx = blockIdx.x;
    int u = bx >> 3, part = bx & 7;
    int tap = u >> 6, r = u & 63, cob = r >> 4, kci = r & 15;
    int within = part * 256 + threadIdx.x;
    int blk = within >> 6, s = within & 63, lane = s >> 1, br = s & 1;
    int n = (blk & 15) * 8 + (lane >> 2);
    int kc = blk >> 4;
    int kk = kc * 16 + ((lane & 3) << 1) + (br << 3);
    int ci = kci * 32 + kk, co = cob * 128 + n;
    float w0 = cw[((size_t)tap * CH + ci) * CH + co];
    float w1 = cw[((size_t)tap * CH + ci + 1) * CH + co];
    uint32_t h = pack_f16(w0, w1);
    float2 back = unpack_f16(h);
    uint32_t l = pack_f16(w0 - back.x, w1 - back.y);
    size_t base = ((((size_t)tap * 4 + cob) * 16 + kci) * 32 + blk) * 128 + lane * 4 + br;
    out[base] = h;
    out[base + 2] = l;
}

__global__ void k_presplit_x(const float* __restrict__ x) {
    int id = blockIdx.x * 256 + threadIdx.x;
    int p2 = id & 255;
    int pix = id >> 8;
    int b = pix >> 10;
    int ci = p2 * 2;
    float v0 = x[(size_t)pix * CH + ci] * (g_s1[b][ci] * WSCALE);
    float v1 = x[(size_t)pix * CH + ci + 1] * (g_s1[b][ci + 1] * WSCALE);
    g_xh[id] = pack_f16(v0, v1);
}

struct Taps { int n; int t[9]; int di[9]; int dj[9]; };
struct Taps4 { Taps c[4]; };

// Implicit-GEMM conv: CTA tile M=256 pixels (16x16) x N=128 couts.
// 8 warps: 4 along M x 2 along N -> 64x64 warp tile. A fp16 single, B fp16 2-term.
#define BLK 132
#define SBU ((32 + 32) * BLK)
#define SBB (SBU * 4)
#define GSMEM (2 * SBB)

template <int MODE>
__global__ __launch_bounds__(256, 1) void k_gemm(
    Taps4 t4, const float* __restrict__ noise, const float* __restrict__ snp,
    const float* __restrict__ biasp, float* __restrict__ outp) {
    constexpr int HI = MODE ? HOUT : HIN;
    constexpr int WI = MODE ? WOUT : WIN;
    extern __shared__ uint32_t smu[];
    __shared__ float s_dv[128], s_sn[128], s_bb[128];

    const int tid = threadIdx.x, lane = tid & 31, wid = tid >> 5;
    const int wm = wid & 3, wn = wid >> 2;
    const int b = blockIdx.z, co0 = blockIdx.x * 128;
    int pb, qb, cls = 0;
    if (MODE) { pb = (blockIdx.y >> 2) * 16; qb = (blockIdx.y & 3) * 16; }
    else {
        cls = blockIdx.y >> 2;
        int yt = blockIdx.y & 3;
        pb = (yt >> 1) * 16; qb = (yt & 1) * 16;
    }
    const Taps& taps = t4.c[MODE ? 0 : cls];
    const int uo = cls >> 1, vo = cls & 1;

    const uint32_t* axh = MODE ? g_x1h : g_xh;
    const uint32_t* wsp = MODE ? g_wspB : g_wspA;

    if (MODE && tid < 128) {
        s_dv[tid] = g_d2[b][co0 + tid];
        s_sn[tid] = snp[co0 + tid];
        s_bb[tid] = biasp[co0 + tid];
    }

    const uint32_t S0 = smem_u32(smu);
    const uint32_t AHr = 0, BHr = 32 * BLK * 4;

    // A staging: 1 thread = 1 pixel (all 32 k)
    const int arow = tid;
    const int apr = arow >> 4, apc = arow & 15;
    const int ar8 = (arow >> 3) & 1;
    const int jrot = (tid >> 1) & 3;  // per-thread j phase (bank spread)

    float acc[4][8][4];
#pragma unroll
    for (int i = 0; i < 4; i++)
#pragma unroll
        for (int j = 0; j < 8; j++)
#pragma unroll
            for (int k = 0; k < 4; k++) acc[i][j][k] = 0.f;

    const int nkb = taps.n * 16;

    auto stageB = [&](int kb, uint32_t off) {
        const int tp = kb >> 4, kci = kb & 15;
        const uint32_t* wb =
            wsp + ((((size_t)taps.t[tp] * 4 + blockIdx.x) * 16 + kci) * 32) * 128;
#pragma unroll
        for (int c = 0; c < 4; c++) {
            int l16 = tid + c * 256;
            int blk = l16 >> 5, in16 = l16 & 31;
            cpa16(S0 + off + BHr + (uint32_t)(blk * (BLK * 4) + in16 * 16),
                  wb + blk * 128 + in16 * 4);
        }
        CP_COMMIT();
    };
    auto loadA = [&](int kb, uint4* hv) {
        const int tp = kb >> 4, kci = kb & 15;
        int gp = pb + apr + taps.di[tp], gq = qb + apc + taps.dj[tp];
        if ((unsigned)gp < (unsigned)HI && (unsigned)gq < (unsigned)WI) {
            size_t o = ((size_t)(b * HI + gp) * WI + gq) * 256 + kci * 16;
            hv[0] = *(const uint4*)(axh + o);
            hv[1] = *(const uint4*)(axh + o + 4);
            hv[2] = *(const uint4*)(axh + o + 8);
            hv[3] = *(const uint4*)(axh + o + 12);
        } else {
            hv[0] = hv[1] = hv[2] = hv[3] = make_uint4(0u, 0u, 0u, 0u);
        }
    };
    auto storeA = [&](uint32_t off, const uint4* hv) {
        const uint32_t abase = S0 + off + AHr + (uint32_t)((arow >> 4) * BLK) * 4;
        const uint32_t* hvp = (const uint32_t*)hv;
#pragma unroll
        for (int i = 0; i < 16; i++) {
            int j = (i + jrot) & 15;  // rotated order spreads STS banks
            uint32_t blkoff = (uint32_t)((j >> 3) * 16 * BLK) * 4;
            uint32_t inb = ((((arow & 7) << 2) | (j & 3)) << 4) +
                           ((ar8 | (((j >> 2) & 1) << 1)) << 2);
            sts32(abase + blkoff + inb, hvp[j]);
        }
    };

    {
        stageB(0, 0);
        uint4 hv[4];
        loadA(0, hv);
        storeA(0, hv);
    }

    for (int kb = 0; kb < nkb; kb++) {
        const uint32_t off = (kb & 1) ? SBB : 0;
        const uint32_t offn = (kb & 1) ? 0 : SBB;
        CP_WAIT0();
        __syncthreads();
        const bool hasnext = (kb + 1 < nkb);
        uint4 hv[4];
        if (hasnext) {
            stageB(kb + 1, offn);
            loadA(kb + 1, hv);
        }
#pragma unroll
        for (int kc = 0; kc < 2; kc++) {
            uint32_t ah[4][4];
#pragma unroll
            for (int mt = 0; mt < 4; mt++) {
                uint32_t ba = (uint32_t)((kc * 16 + (wm << 2) + mt) * BLK) * 4 + lane * 16;
                lds128(ah[mt], S0 + off + AHr + ba);
            }
#pragma unroll
            for (int nt = 0; nt < 8; nt++) {
                uint32_t bbf[4];
                lds128(bbf, S0 + off + BHr +
                                (uint32_t)((kc * 16 + (wn << 3) + nt) * BLK) * 4 + lane * 16);
#pragma unroll
                for (int mt = 0; mt < 4; mt++) {
                    mma16(acc[mt][nt], ah[mt], bbf[0], bbf[1]);
                    mma16(acc[mt][nt], ah[mt], bbf[2], bbf[3]);
                }
            }
        }
        if (hasnext) storeA(offn, hv);
        __syncthreads();
    }

    const int r0 = wm * 64 + (lane >> 2);
    const int cb = wn * 64 + (lane & 3) * 2;
#pragma unroll
    for (int mt = 0; mt < 4; mt++)
#pragma unroll
        for (int half = 0; half < 2; half++) {
            int m = r0 + mt * 16 + half * 8;
            int pr = m >> 4, pc = m & 15;
            int p, q;
            if (MODE) { p = pb + pr; q = qb + pc; }
            else      { p = 2 * (pb + pr) + uo; q = 2 * (qb + pc) + vo; }
            size_t base = (((size_t)b * HOUT + p) * WOUT + q) * CH + co0;
            float nz = MODE ? noise[((size_t)b * HOUT + p) * WOUT + q] : 0.f;
#pragma unroll
            for (int nt = 0; nt < 8; nt++) {
                int col = cb + nt * 8;
                float v0 = acc[mt][nt][half * 2 + 0];
                float v1 = acc[mt][nt][half * 2 + 1];
                float2 o;
                if (MODE) {
                    o.x = lrelu(v0 * s_dv[col] + s_sn[col] * nz + s_bb[col]);
                    o.y = lrelu(v1 * s_dv[col + 1] + s_sn[col + 1] * nz + s_bb[col + 1]);
                    *(float2*)&outp[base + col] = o;
                } else {
                    o.x = v0; o.y = v1;
                    *(float2*)&g_y[base + col] = o;
                }
            }
        }
}

#define BSMEM ((121 * 64 + 88 * 64) * 4)
__global__ __launch_bounds__(256) void k_blur(
    const float* __restrict__ noise1, const float* __restrict__ sn1,
    const float* __restrict__ bias1) {
    extern __shared__ float bsm[];
    float* sin_ = bsm;
    float* shn = bsm + 121 * 64;
    const int tid = threadIdx.x;
    const int cob = blockIdx.x;
    const int tile = blockIdx.y;
    const int b = blockIdx.z;
    const int p0 = (tile >> 3) * 8, q0 = (tile & 7) * 8;
    const int cbase = cob * 64;
    const float fw[4] = {1.f, 3.f, 3.f, 1.f};

    for (int idx = tid; idx < 121 * 16; idx += 256) {
        int pix = idx >> 4, c4 = idx & 15;
        int r = pix / 11, cc = pix - r * 11;
        int gp = p0 - 1 + r, gq = q0 - 1 + cc;
        float4 v = make_float4(0.f, 0.f, 0.f, 0.f);
        if ((unsigned)gp < HOUT && (unsigned)gq < WOUT)
            v = *(const float4*)&g_y[(((size_t)b * HOUT + gp) * WOUT + gq) * CH + cbase + c4 * 4];
        *(float4*)&sin_[pix * 64 + c4 * 4] = v;
    }
    __syncthreads();
    for (int idx = tid; idx < 88 * 16; idx += 256) {
        int c4 = idx & 15, rq = idx >> 4;
        int r = rq >> 3, qc = rq & 7;
        float4 a = make_float4(0.f, 0.f, 0.f, 0.f);
#pragma unroll
        for (int ew = 0; ew < 4; ew++) {
            float4 v = *(const float4*)&sin_[(r * 11 + qc + ew) * 64 + c4 * 4];
            a.x += v.x * fw[ew]; a.y += v.y * fw[ew];
            a.z += v.z * fw[ew]; a.w += v.w * fw[ew];
        }
        *(float4*)&shn[rq * 64 + c4 * 4] = a;
    }
    __syncthreads();
    const float inv16 = 0.0625f;
    for (int idx = tid; idx < 64 * 16; idx += 256) {
        int c4 = idx & 15, opix = idx >> 4;
        int pp = opix >> 3, qc = opix & 7;
        float4 a = make_float4(0.f, 0.f, 0.f, 0.f);
#pragma unroll
        for (int eh = 0; eh < 4; eh++) {
            float4 v = *(const float4*)&shn[((pp + eh) * 8 + qc) * 64 + c4 * 4];
            a.x += v.x * fw[eh]; a.y += v.y * fw[eh];
            a.z += v.z * fw[eh]; a.w += v.w * fw[eh];
        }
        int p = p0 + pp, q = q0 + qc;
        int c = cbase + c4 * 4;
        float4 dv = *(const float4*)&g_d1[b][c];
        float4 sn = *(const float4*)&sn1[c];
        float4 bb = *(const float4*)&bias1[c];
        float nz = noise1[((size_t)b * HOUT + p) * WOUT + q];
        float o0 = lrelu(a.x * inv16 * dv.x + sn.x * nz + bb.x);
        float o1 = lrelu(a.y * inv16 * dv.y + sn.y * nz + bb.y);
        float o2 = lrelu(a.z * inv16 * dv.z + sn.z * nz + bb.z);
        float o3 = lrelu(a.w * inv16 * dv.w + sn.w * nz + bb.w);
        float a0 = o0 * (g_s2[b][c] * WSCALE);
        float a1 = o1 * (g_s2[b][c + 1] * WSCALE);
        float a2 = o2 * (g_s2[b][c + 2] * WSCALE);
        float a3 = o3 * (g_s2[b][c + 3] * WSCALE);
        size_t pi = (((size_t)b * HOUT + p) * WOUT + q) * 256 + (c >> 1);
        g_x1h[pi] = pack_f16(a0, a1);
        g_x1h[pi + 1] = pack_f16(a2, a3);
    }
}

__global__ void k_rgb(const float* __restrict__ x2, const float* __restrict__ wr,
                      const float* __restrict__ br, float* __restrict__ rgb) {
    int b = blockIdx.y, tid = threadIdx.x;
    __shared__ float wc[CH * 3];
    const float wscale = 0.044194173824159216f;
    for (int k = tid; k < CH * 3; k += 256) {
        int ci = k / 3;
        wc[k] = g_sr[b][ci] * wscale * wr[k];
    }
    __syncthreads();
    int warp = tid >> 5, lane = tid & 31;
    int pix = blockIdx.x * 8 + warp;
    const float* xp = x2 + ((size_t)b * HOUT * WOUT + pix) * CH;
    float a0 = 0.f, a1 = 0.f, a2 = 0.f;
    for (int ci = lane; ci < CH; ci += 32) {
        float v = xp[ci];
        a0 = fmaf(v, wc[ci * 3 + 0], a0);
        a1 = fmaf(v, wc[ci * 3 + 1], a1);
        a2 = fmaf(v, wc[ci * 3 + 2], a2);
    }
#pragma unroll
    for (int o = 16; o; o >>= 1) {
        a0 += __shfl_xor_sync(0xffffffffu, a0, o);
        a1 += __shfl_xor_sync(0xffffffffu, a1, o);
        a2 += __shfl_xor_sync(0xffffffffu, a2, o);
    }
    if (lane == 0) {
        size_t base = ((size_t)b * HOUT * WOUT + pix) * 3;
        rgb[base + 0] = lrelu(a0 + br[0]);
        rgb[base + 1] = lrelu(a1 + br[1]);
        rgb[base + 2] = lrelu(a2 + br[2]);
    }
}

extern "C" void kernel_launch(void* const* d_in, const int* in_sizes, int n_in,
                              void* d_out, int out_size) {
    const float* x       = (const float*)d_in[0];
    const float* w       = (const float*)d_in[1];
    const float* noise1  = (const float*)d_in[2];
    const float* noise2  = (const float*)d_in[3];
    const float* fcl1_w  = (const float*)d_in[4];
    const float* fcl1_b  = (const float*)d_in[5];
    const float* conv1_w = (const float*)d_in[6];
    const float* sn1     = (const float*)d_in[7];
    const float* bias1   = (const float*)d_in[8];
    const float* fcl2_w  = (const float*)d_in[9];
    const float* fcl2_b  = (const float*)d_in[10];
    const float* conv2_w = (const float*)d_in[11];
    const float* sn2     = (const float*)d_in[12];
    const float* bias2   = (const float*)d_in[13];
    const float* fclr_w  = (const float*)d_in[14];
    const float* fclr_b  = (const float*)d_in[15];
    const float* convr_w = (const float*)d_in[16];
    const float* biasr   = (const float*)d_in[17];
    float* out = (float*)d_out;
    float* xpart = out;
    float* rgbpart = out + (size_t)BATCH * HOUT * WOUT * CH;

    cudaFuncSetAttribute(k_gemm<0>, cudaFuncAttributeMaxDynamicSharedMemorySize, GSMEM);
    cudaFuncSetAttribute(k_gemm<1>, cudaFuncAttributeMaxDynamicSharedMemorySize, GSMEM);
    cudaFuncSetAttribute(k_blur, cudaFuncAttributeMaxDynamicSharedMemorySize, BSMEM);

    Taps4 tc{};
    tc.c[0].n = 4;
    tc.c[0].t[0] = 0; tc.c[0].di[0] = -1; tc.c[0].dj[0] = -1;
    tc.c[0].t[1] = 2; tc.c[0].di[1] = -1; tc.c[0].dj[1] = 0;
    tc.c[0].t[2] = 6; tc.c[0].di[2] = 0;  tc.c[0].dj[2] = -1;
    tc.c[0].t[3] = 8; tc.c[0].di[3] = 0;  tc.c[0].dj[3] = 0;
    tc.c[1].n = 2;
    tc.c[1].t[0] = 1; tc.c[1].di[0] = -1; tc.c[1].dj[0] = 0;
    tc.c[1].t[1] = 7; tc.c[1].di[1] = 0;  tc.c[1].dj[1] = 0;
    tc.c[2].n = 2;
    tc.c[2].t[0] = 3; tc.c[2].di[0] = 0; tc.c[2].dj[0] = -1;
    tc.c[2].t[1] = 5; tc.c[2].di[1] = 0; tc.c[2].dj[1] = 0;
    tc.c[3].n = 1;
    tc.c[3].t[0] = 4; tc.c[3].di[0] = 0; tc.c[3].dj[0] = 0;

    Taps4 t2{};
    t2.c[0].n = 9;
    for (int dh = 0; dh < 3; dh++)
        for (int dw = 0; dw < 3; dw++) {
            int i = dh * 3 + dw;
            t2.c[0].t[i] = i; t2.c[0].di[i] = dh - 1; t2.c[0].dj[i] = dw - 1;
        }

    // Order keeps ncu capture slot on k_gemm<0> (4th launch).
    k_styles<<<dim3(BATCH, 3), 512>>>(w, fcl1_w, fcl1_b, fcl2_w, fcl2_b, fclr_w, fclr_b);
    k_presplit_x<<<16384, 256>>>(x);
    k_wsplit<<<4608, 256>>>(conv1_w, 0);
    k_gemm<0><<<dim3(4, 16, BATCH), 256, GSMEM>>>(tc, nullptr, nullptr, nullptr, nullptr);
    k_wsplit<<<4608, 256>>>(conv2_w, 1);
    k_wsq<<<(CH * CH) / 256, 256>>>(conv1_w, conv2_w);
    k_demod<<<dim3(BATCH, 2), 512>>>();
    k_blur<<<dim3(8, 64, BATCH), 256, BSMEM>>>(noise1, sn1, bias1);
    k_gemm<1><<<dim3(4, 16, BATCH), 256, GSMEM>>>(t2, noise2, sn2, bias2, xpart);
    k_rgb<<<dim3(HOUT * WOUT / 8, BATCH), 256>>>(xpart, convr_w, biasr, rgbpart);
}

// round 17
// speedup vs baseline: 1.2909x; 1.2909x over previous
#include <cuda_runtime.h>
#include <cuda_fp16.h>
#include <cstdint>

#define BATCH 16
#define HIN 32
#define WIN 32
#define CH 512
#define HOUT 64
#define WOUT 64
#define WSCALE 0.014731391274719742f

__device__ float g_s1[BATCH][CH];
__device__ float g_s2[BATCH][CH];
__device__ float g_sr[BATCH][CH];
__device__ float g_d1[BATCH][CH];
__device__ float g_d2[BATCH][CH];
__device__ float g_wsq1[CH * CH];
__device__ float g_wsq2[CH * CH];
__device__ float g_y[(size_t)BATCH * HOUT * WOUT * CH];
__device__ uint32_t g_xh[(size_t)BATCH * HIN * WIN * 256];
__device__ uint32_t g_x1h[(size_t)BATCH * HOUT * WOUT * 256];
#define WSPN (9 * 4 * 16 * 32 * 128)
__device__ uint32_t g_wspA[WSPN];
__device__ uint32_t g_wspB[WSPN];

__device__ __forceinline__ float lrelu(float v) { return v > 0.f ? v : 0.2f * v; }

__device__ __forceinline__ uint32_t smem_u32(const void* p) {
    uint32_t a;
    asm("{ .reg .u64 t; cvta.to.shared.u64 t, %1; cvt.u32.u64 %0, t; }" : "=r"(a) : "l"(p));
    return a;
}
__device__ __forceinline__ uint32_t pack_f16(float f0, float f1) {
    __half2 h = __floats2half2_rn(f0, f1);
    return *(uint32_t*)&h;
}
__device__ __forceinline__ float2 unpack_f16(uint32_t p) {
    __half2 h = *(__half2*)&p;
    return __half22float2(h);
}
__device__ __forceinline__ void mma16(float* d, const uint32_t* a, uint32_t b0, uint32_t b1) {
    asm volatile(
        "mma.sync.aligned.m16n8k16.row.col.f32.f16.f16.f32 "
        "{%0,%1,%2,%3},{%4,%5,%6,%7},{%8,%9},{%0,%1,%2,%3};"
        : "+f"(d[0]), "+f"(d[1]), "+f"(d[2]), "+f"(d[3])
        : "r"(a[0]), "r"(a[1]), "r"(a[2]), "r"(a[3]), "r"(b0), "r"(b1));
}
__device__ __forceinline__ void lds128(uint32_t* r, uint32_t a) {
    asm volatile("ld.shared.v4.b32 {%0,%1,%2,%3},[%4];"
                 : "=r"(r[0]), "=r"(r[1]), "=r"(r[2]), "=r"(r[3]) : "r"(a));
}
__device__ __forceinline__ void sts32(uint32_t a, uint32_t v) {
    asm volatile("st.shared.b32 [%0],%1;" :: "r"(a), "r"(v) : "memory");
}
__device__ __forceinline__ void cpa16(uint32_t dst, const uint32_t* src) {
    asm volatile("cp.async.cg.shared.global [%0], [%1], 16;"
                 :: "r"(dst), "l"(src) : "memory");
}
#define CP_COMMIT() asm volatile("cp.async.commit_group;" ::: "memory")
#define CP_WAIT0() asm volatile("cp.async.wait_group 0;" ::: "memory")

__global__ void k_styles(const float* __restrict__ w,
                         const float* __restrict__ f1w, const float* __restrict__ f1b,
                         const float* __restrict__ f2w, const float* __restrict__ f2b,
                         const float* __restrict__ frw, const float* __restrict__ frb) {
    int b = blockIdx.x, which = blockIdx.y, co = threadIdx.x;
    const float* fw = which == 0 ? f1w : (which == 1 ? f2w : frw);
    const float* fb = which == 0 ? f1b : (which == 1 ? f2b : frb);
    __shared__ float sw_[CH];
    sw_[co] = w[b * CH + co];
    __syncthreads();
    float acc = 0.f;
#pragma unroll 4
    for (int ci = 0; ci < CH; ci++) acc = fmaf(sw_[ci], fw[ci * CH + co], acc);
    float v = acc * 0.044194173824159216f + fb[co];
    if (which == 0) g_s1[b][co] = v;
    else if (which == 1) g_s2[b][co] = v;
    else g_sr[b][co] = v;
}

__global__ void k_wsq(const float* __restrict__ w1, const float* __restrict__ w2) {
    int idx = blockIdx.x * 256 + threadIdx.x;
    const float ws2 = 1.0f / 4608.0f;
    float a1 = 0.f, a2 = 0.f;
#pragma unroll
    for (int t = 0; t < 9; t++) {
        float v1 = w1[(size_t)t * CH * CH + idx];
        a1 = fmaf(v1, v1, a1);
        float v2 = w2[(size_t)t * CH * CH + idx];
        a2 = fmaf(v2, v2, a2);
    }
    g_wsq1[idx] = a1 * ws2;
    g_wsq2[idx] = a2 * ws2;
}

__global__ void k_demod() {
    int b = blockIdx.x, which = blockIdx.y, co = threadIdx.x;
    __shared__ float ss[CH];
    float s = which ? g_s2[b][co] : g_s1[b][co];
    ss[co] = s * s;
    __syncthreads();
    const float* wsq = which ? g_wsq2 : g_wsq1;
    float acc = 0.f;
#pragma unroll 4
    for (int ci = 0; ci < CH; ci++) acc = fmaf(ss[ci], wsq[ci * CH + co], acc);
    float d = rsqrtf(acc + 1e-8f);
    if (which) g_d2[b][co] = d;
    else g_d1[b][co] = d;
}

__global__ void k_wsplit(const float* __restrict__ cw, int which) {
    uint32_t* __restrict__ out = which ? g_wspB : g_wspA;
    int bx = blockIdx.x;
    int u = bx >> 3, part = bx & 7;
    int tap = u >> 6, r = u & 63, cob = r >> 4, kci = r & 15;
    int within = part * 256 + threadIdx.x;
    int blk = within >> 6, s = within & 63, lane = s >> 1, br = s & 1;
    int n = (blk & 15) * 8 + (lane >> 2);
    int kc = blk >> 4;
    int kk = kc * 16 + ((lane & 3) << 1) + (br << 3);
    int ci = kci * 32 + kk, co = cob * 128 + n;
    float w0 = cw[((size_t)tap * CH + ci) * CH + co];
    float w1 = cw[((size_t)tap * CH + ci + 1) * CH + co];
    uint32_t h = pack_f16(w0, w1);
    float2 back = unpack_f16(h);
    uint32_t l = pack_f16(w0 - back.x, w1 - back.y);
    size_t base = ((((size_t)tap * 4 + cob) * 16 + kci) * 32 + blk) * 128 + lane * 4 + br;
    out[base] = h;
    out[base + 2] = l;
}

__global__ void k_presplit_x(const float* __restrict__ x) {
    int id = blockIdx.x * 256 + threadIdx.x;
    int p2 = id & 255;
    int pix = id >> 8;
    int b = pix >> 10;
    int ci = p2 * 2;
    float v0 = x[(size_t)pix * CH + ci] * (g_s1[b][ci] * WSCALE);
    float v1 = x[(size_t)pix * CH + ci + 1] * (g_s1[b][ci + 1] * WSCALE);
    g_xh[id] = pack_f16(v0, v1);
}

struct Taps { int n; int t[9]; int di[9]; int dj[9]; };
struct Taps4 { Taps c[4]; };

// Implicit-GEMM conv: CTA 128x128, 8 warps as 2(M) x 4(N) -> warp tile 64x32.
// A fp16 single, B fp16 2-term split. Double-buffered, 2 CTAs/SM.
#define BLK 132
#define SBU ((16 + 32) * BLK)
#define SBB (SBU * 4)
#define GSMEM (2 * SBB)

template <int MODE>
__global__ __launch_bounds__(256, 2) void k_gemm(
    Taps4 t4, const float* __restrict__ noise, const float* __restrict__ snp,
    const float* __restrict__ biasp, float* __restrict__ outp) {
    constexpr int HI = MODE ? HOUT : HIN;
    constexpr int WI = MODE ? WOUT : WIN;
    extern __shared__ uint32_t smu[];
    __shared__ float s_dv[128], s_sn[128], s_bb[128];

    const int tid = threadIdx.x, lane = tid & 31, wid = tid >> 5;
    const int wm = wid & 1, wn = wid >> 1;
    const int b = blockIdx.z, co0 = blockIdx.x * 128;
    int pb, qb, cls = 0;
    if (MODE) { pb = (blockIdx.y >> 2) * 8; qb = (blockIdx.y & 3) * 16; }
    else {
        cls = blockIdx.y >> 3;
        int yt = blockIdx.y & 7;
        pb = (yt >> 1) * 8; qb = (yt & 1) * 16;
    }
    const Taps& taps = t4.c[MODE ? 0 : cls];
    const int uo = cls >> 1, vo = cls & 1;

    const uint32_t* axh = MODE ? g_x1h : g_xh;
    const uint32_t* wsp = MODE ? g_wspB : g_wspA;

    if (MODE && tid < 128) {
        s_dv[tid] = g_d2[b][co0 + tid];
        s_sn[tid] = snp[co0 + tid];
        s_bb[tid] = biasp[co0 + tid];
    }

    const uint32_t S0 = smem_u32(smu);
    const uint32_t AHr = 0, BHr = 16 * BLK * 4;

    const int arow = tid >> 1, akhalf8 = (tid & 1) * 8;
    const int arg = arow >> 4, ar8 = (arow >> 3) & 1, alb = (arow & 7) << 2;
    const int apr = arow >> 4, apc = arow & 15;
    const uint32_t arel = (uint32_t)(((tid & 1) * 8 + arg) * BLK) * 4;

    float acc[4][4][4];
#pragma unroll
    for (int i = 0; i < 4; i++)
#pragma unroll
        for (int j = 0; j < 4; j++)
#pragma unroll
            for (int k = 0; k < 4; k++) acc[i][j][k] = 0.f;

    const int nkb = taps.n * 16;

    auto stageB = [&](int kb, uint32_t off) {
        const int tp = kb >> 4, kci = kb & 15;
        const uint32_t* wb =
            wsp + ((((size_t)taps.t[tp] * 4 + blockIdx.x) * 16 + kci) * 32) * 128;
#pragma unroll
        for (int c = 0; c < 4; c++) {
            int l16 = tid + c * 256;
            int blk = l16 >> 5, in16 = l16 & 31;
            cpa16(S0 + off + BHr + (uint32_t)(blk * (BLK * 4) + in16 * 16),
                  wb + blk * 128 + in16 * 4);
        }
        CP_COMMIT();
    };
    auto loadA = [&](int kb, uint4* hv) {
        const int tp = kb >> 4, kci = kb & 15;
        int gp = pb + apr + taps.di[tp], gq = qb + apc + taps.dj[tp];
        if ((unsigned)gp < (unsigned)HI && (unsigned)gq < (unsigned)WI) {
            size_t o = ((size_t)(b * HI + gp) * WI + gq) * 256 + kci * 16 + akhalf8;
            hv[0] = *(const uint4*)(axh + o);
            hv[1] = *(const uint4*)(axh + o + 4);
        } else {
            hv[0] = hv[1] = make_uint4(0u, 0u, 0u, 0u);
        }
    };
    auto storeA = [&](uint32_t off, const uint4* hv) {
        uint32_t ab = S0 + off + AHr + arel;
#define APUT(J, HV)                                                                  \
    {                                                                                \
        uint32_t off_ = (((alb | ((J) & 3)) << 2) + (ar8 | (((J) >> 2) << 1))) << 2; \
        sts32(ab + off_, (HV));                                                      \
    }
        APUT(0, hv[0].x) APUT(1, hv[0].y) APUT(2, hv[0].z) APUT(3, hv[0].w)
        APUT(4, hv[1].x) APUT(5, hv[1].y) APUT(6, hv[1].z) APUT(7, hv[1].w)
#undef APUT
    };

    {
        stageB(0, 0);
        uint4 hv[2];
        loadA(0, hv);
        storeA(0, hv);
    }

    for (int kb = 0; kb < nkb; kb++) {
        const uint32_t off = (kb & 1) ? SBB : 0;
        const uint32_t offn = (kb & 1) ? 0 : SBB;
        CP_WAIT0();
        __syncthreads();
        const bool hasnext = (kb + 1 < nkb);
        uint4 hv[2];
        if (hasnext) {
            stageB(kb + 1, offn);   // LDGSTS runs under the MMAs below
            loadA(kb + 1, hv);      // LDG latency hidden under the MMAs
        }
#pragma unroll
        for (int kc = 0; kc < 2; kc++) {
            uint32_t ah[4][4];
#pragma unroll
            for (int mt = 0; mt < 4; mt++) {
                uint32_t ba = (uint32_t)((kc * 8 + (wm << 2) + mt) * BLK) * 4 + lane * 16;
                lds128(ah[mt], S0 + off + AHr + ba);
            }
#pragma unroll
            for (int nt = 0; nt < 4; nt++) {
                uint32_t bbf[4];
                lds128(bbf, S0 + off + BHr +
                                (uint32_t)((kc * 16 + (wn << 2) + nt) * BLK) * 4 + lane * 16);
#pragma unroll
                for (int mt = 0; mt < 4; mt++) {
                    mma16(acc[mt][nt], ah[mt], bbf[0], bbf[1]);
                    mma16(acc[mt][nt], ah[mt], bbf[2], bbf[3]);
                }
            }
        }
        if (hasnext) storeA(offn, hv);
        __syncthreads();
    }

    const int r0 = wm * 64 + (lane >> 2);
    const int cb = wn * 32 + (lane & 3) * 2;
#pragma unroll
    for (int mt = 0; mt < 4; mt++)
#pragma unroll
        for (int half = 0; half < 2; half++) {
            int m = r0 + mt * 16 + half * 8;
            int pr = m >> 4, pc = m & 15;
            int p, q;
            if (MODE) { p = pb + pr; q = qb + pc; }
            else      { p = 2 * (pb + pr) + uo; q = 2 * (qb + pc) + vo; }
            size_t base = (((size_t)b * HOUT + p) * WOUT + q) * CH + co0;
            float nz = MODE ? noise[((size_t)b * HOUT + p) * WOUT + q] : 0.f;
#pragma unroll
            for (int nt = 0; nt < 4; nt++) {
                int col = cb + nt * 8;
                float v0 = acc[mt][nt][half * 2 + 0];
                float v1 = acc[mt][nt][half * 2 + 1];
                float2 o;
                if (MODE) {
                    o.x = lrelu(v0 * s_dv[col] + s_sn[col] * nz + s_bb[col]);
                    o.y = lrelu(v1 * s_dv[col + 1] + s_sn[col + 1] * nz + s_bb[col + 1]);
                    *(float2*)&outp[base + col] = o;
                } else {
                    o.x = v0; o.y = v1;
                    *(float2*)&g_y[base + col] = o;
                }
            }
        }
}

#define BSMEM ((121 * 64 + 88 * 64) * 4)
__global__ __launch_bounds__(256) void k_blur(
    const float* __restrict__ noise1, const float* __restrict__ sn1,
    const float* __restrict__ bias1) {
    extern __shared__ float bsm[];
    float* sin_ = bsm;
    float* shn = bsm + 121 * 64;
    const int tid = threadIdx.x;
    const int cob = blockIdx.x;
    const int tile = blockIdx.y;
    const int b = blockIdx.z;
    const int p0 = (tile >> 3) * 8, q0 = (tile & 7) * 8;
    const int cbase = cob * 64;
    const float fw[4] = {1.f, 3.f, 3.f, 1.f};

    for (int idx = tid; idx < 121 * 16; idx += 256) {
        int pix = idx >> 4, c4 = idx & 15;
        int r = pix / 11, cc = pix - r * 11;
        int gp = p0 - 1 + r, gq = q0 - 1 + cc;
        float4 v = make_float4(0.f, 0.f, 0.f, 0.f);
        if ((unsigned)gp < HOUT && (unsigned)gq < WOUT)
            v = *(const float4*)&g_y[(((size_t)b * HOUT + gp) * WOUT + gq) * CH + cbase + c4 * 4];
        *(float4*)&sin_[pix * 64 + c4 * 4] = v;
    }
    __syncthreads();
    for (int idx = tid; idx < 88 * 16; idx += 256) {
        int c4 = idx & 15, rq = idx >> 4;
        int r = rq >> 3, qc = rq & 7;
        float4 a = make_float4(0.f, 0.f, 0.f, 0.f);
#pragma unroll
        for (int ew = 0; ew < 4; ew++) {
            float4 v = *(const float4*)&sin_[(r * 11 + qc + ew) * 64 + c4 * 4];
            a.x += v.x * fw[ew]; a.y += v.y * fw[ew];
            a.z += v.z * fw[ew]; a.w += v.w * fw[ew];
        }
        *(float4*)&shn[rq * 64 + c4 * 4] = a;
    }
    __syncthreads();
    const float inv16 = 0.0625f;
    for (int idx = tid; idx < 64 * 16; idx += 256) {
        int c4 = idx & 15, opix = idx >> 4;
        int pp = opix >> 3, qc = opix & 7;
        float4 a = make_float4(0.f, 0.f, 0.f, 0.f);
#pragma unroll
        for (int eh = 0; eh < 4; eh++) {
            float4 v = *(const float4*)&shn[((pp + eh) * 8 + qc) * 64 + c4 * 4];
            a.x += v.x * fw[eh]; a.y += v.y * fw[eh];
            a.z += v.z * fw[eh]; a.w += v.w * fw[eh];
        }
        int p = p0 + pp, q = q0 + qc;
        int c = cbase + c4 * 4;
        float4 dv = *(const float4*)&g_d1[b][c];
        float4 sn = *(const float4*)&sn1[c];
        float4 bb = *(const float4*)&bias1[c];
        float nz = noise1[((size_t)b * HOUT + p) * WOUT + q];
        float o0 = lrelu(a.x * inv16 * dv.x + sn.x * nz + bb.x);
        float o1 = lrelu(a.y * inv16 * dv.y + sn.y * nz + bb.y);
        float o2 = lrelu(a.z * inv16 * dv.z + sn.z * nz + bb.z);
        float o3 = lrelu(a.w * inv16 * dv.w + sn.w * nz + bb.w);
        float a0 = o0 * (g_s2[b][c] * WSCALE);
        float a1 = o1 * (g_s2[b][c + 1] * WSCALE);
        float a2 = o2 * (g_s2[b][c + 2] * WSCALE);
        float a3 = o3 * (g_s2[b][c + 3] * WSCALE);
        size_t pi = (((size_t)b * HOUT + p) * WOUT + q) * 256 + (c >> 1);
        g_x1h[pi] = pack_f16(a0, a1);
        g_x1h[pi + 1] = pack_f16(a2, a3);
    }
}

__global__ void k_rgb(const float* __restrict__ x2, const float* __restrict__ wr,
                      const float* __restrict__ br, float* __restrict__ rgb) {
    int b = blockIdx.y, tid = threadIdx.x;
    __shared__ float wc[CH * 3];
    const float wscale = 0.044194173824159216f;
    for (int k = tid; k < CH * 3; k += 256) {
        int ci = k / 3;
        wc[k] = g_sr[b][ci] * wscale * wr[k];
    }
    __syncthreads();
    int warp = tid >> 5, lane = tid & 31;
    int pix = blockIdx.x * 8 + warp;
    const float* xp = x2 + ((size_t)b * HOUT * WOUT + pix) * CH;
    float a0 = 0.f, a1 = 0.f, a2 = 0.f;
    for (int ci = lane; ci < CH; ci += 32) {
        float v = xp[ci];
        a0 = fmaf(v, wc[ci * 3 + 0], a0);
        a1 = fmaf(v, wc[ci * 3 + 1], a1);
        a2 = fmaf(v, wc[ci * 3 + 2], a2);
    }
#pragma unroll
    for (int o = 16; o; o >>= 1) {
        a0 += __shfl_xor_sync(0xffffffffu, a0, o);
        a1 += __shfl_xor_sync(0xffffffffu, a1, o);
        a2 += __shfl_xor_sync(0xffffffffu, a2, o);
    }
    if (lane == 0) {
        size_t base = ((size_t)b * HOUT * WOUT + pix) * 3;
        rgb[base + 0] = lrelu(a0 + br[0]);
        rgb[base + 1] = lrelu(a1 + br[1]);
        rgb[base + 2] = lrelu(a2 + br[2]);
    }
}

extern "C" void kernel_launch(void* const* d_in, const int* in_sizes, int n_in,
                              void* d_out, int out_size) {
    const float* x       = (const float*)d_in[0];
    const float* w       = (const float*)d_in[1];
    const float* noise1  = (const float*)d_in[2];
    const float* noise2  = (const float*)d_in[3];
    const float* fcl1_w  = (const float*)d_in[4];
    const float* fcl1_b  = (const float*)d_in[5];
    const float* conv1_w = (const float*)d_in[6];
    const float* sn1     = (const float*)d_in[7];
    const float* bias1   = (const float*)d_in[8];
    const float* fcl2_w  = (const float*)d_in[9];
    const float* fcl2_b  = (const float*)d_in[10];
    const float* conv2_w = (const float*)d_in[11];
    const float* sn2     = (const float*)d_in[12];
    const float* bias2   = (const float*)d_in[13];
    const float* fclr_w  = (const float*)d_in[14];
    const float* fclr_b  = (const float*)d_in[15];
    const float* convr_w = (const float*)d_in[16];
    const float* biasr   = (const float*)d_in[17];
    float* out = (float*)d_out;
    float* xpart = out;
    float* rgbpart = out + (size_t)BATCH * HOUT * WOUT * CH;

    cudaFuncSetAttribute(k_gemm<0>, cudaFuncAttributeMaxDynamicSharedMemorySize, GSMEM);
    cudaFuncSetAttribute(k_gemm<1>, cudaFuncAttributeMaxDynamicSharedMemorySize, GSMEM);
    cudaFuncSetAttribute(k_blur, cudaFuncAttributeMaxDynamicSharedMemorySize, BSMEM);

    Taps4 tc{};
    tc.c[0].n = 4;
    tc.c[0].t[0] = 0; tc.c[0].di[0] = -1; tc.c[0].dj[0] = -1;
    tc.c[0].t[1] = 2; tc.c[0].di[1] = -1; tc.c[0].dj[1] = 0;
    tc.c[0].t[2] = 6; tc.c[0].di[2] = 0;  tc.c[0].dj[2] = -1;
    tc.c[0].t[3] = 8; tc.c[0].di[3] = 0;  tc.c[0].dj[3] = 0;
    tc.c[1].n = 2;
    tc.c[1].t[0] = 1; tc.c[1].di[0] = -1; tc.c[1].dj[0] = 0;
    tc.c[1].t[1] = 7; tc.c[1].di[1] = 0;  tc.c[1].dj[1] = 0;
    tc.c[2].n = 2;
    tc.c[2].t[0] = 3; tc.c[2].di[0] = 0; tc.c[2].dj[0] = -1;
    tc.c[2].t[1] = 5; tc.c[2].di[1] = 0; tc.c[2].dj[1] = 0;
    tc.c[3].n = 1;
    tc.c[3].t[0] = 4; tc.c[3].di[0] = 0; tc.c[3].dj[0] = 0;

    Taps4 t2{};
    t2.c[0].n = 9;
    for (int dh = 0; dh < 3; dh++)
        for (int dw = 0; dw < 3; dw++) {
            int i = dh * 3 + dw;
            t2.c[0].t[i] = i; t2.c[0].di[i] = dh - 1; t2.c[0].dj[i] = dw - 1;
        }

    // Order keeps ncu capture slot on k_gemm<0> (4th launch).
    k_styles<<<dim3(BATCH, 3), 512>>>(w, fcl1_w, fcl1_b, fcl2_w, fcl2_b, fclr_w, fclr_b);
    k_presplit_x<<<16384, 256>>>(x);
    k_wsplit<<<4608, 256>>>(conv1_w, 0);
    k_gemm<0><<<dim3(4, 32, BATCH), 256, GSMEM>>>(tc, nullptr, nullptr, nullptr, nullptr);
    k_wsplit<<<4608, 256>>>(conv2_w, 1);
    k_wsq<<<(CH * CH) / 256, 256>>>(conv1_w, conv2_w);
    k_demod<<<dim3(BATCH, 2), 512>>>();
    k_blur<<<dim3(8, 64, BATCH), 256, BSMEM>>>(noise1, sn1, bias1);
    k_gemm<1><<<dim3(4, 32, BATCH), 256, GSMEM>>>(t2, noise2, sn2, bias2, xpart);
    k_rgb<<<dim3(HOUT * WOUT / 8, BATCH), 256>>>(xpart, convr_w, biasr, rgbpart);
}